// round 1
// baseline (speedup 1.0000x reference)
#include <cuda_runtime.h>
#include <cstdint>

#define HID  1024
#define ITR  4096
#define MTOT 16384

// Intermediate activation buffer (ReLU(X@W1^T + b1)), 16384 x 4096 fp32 = 256 MiB.
// __device__ global = the allowed scratch mechanism (no cudaMalloc).
__device__ float g_inter[(size_t)MTOT * (size_t)ITR];

#define BM 128
#define BN 128
#define BK 32
#define BKP 36                       // +4 pad: conflict-free fragment LDS
#define TILE_F (BM * BKP)            // floats per (stage, operand) tile
#define SMEM_FLOATS (4 * TILE_F)     // 2 stages x (A + B)
#define SMEM_BYTES (SMEM_FLOATS * 4) // 73728 B

__device__ __forceinline__ void cp_async16(uint32_t saddr, const void* gptr) {
    asm volatile("cp.async.cg.shared.global [%0], [%1], 16;\n" :: "r"(saddr), "l"(gptr));
}
__device__ __forceinline__ void cp_commit() {
    asm volatile("cp.async.commit_group;\n");
}
template <int N>
__device__ __forceinline__ void cp_wait() {
    asm volatile("cp.async.wait_group %0;\n" :: "n"(N));
}

__device__ __forceinline__ uint32_t f2tf32(float f) {
    uint32_t r;
    asm("cvt.rna.tf32.f32 %0, %1;\n" : "=r"(r) : "f"(f));
    return r;
}

__device__ __forceinline__ void mma_tf32(float* d, const uint32_t* a, const uint32_t* b) {
    asm volatile(
        "mma.sync.aligned.m16n8k8.row.col.f32.tf32.tf32.f32 "
        "{%0,%1,%2,%3}, {%4,%5,%6,%7}, {%8,%9}, {%0,%1,%2,%3};\n"
        : "+f"(d[0]), "+f"(d[1]), "+f"(d[2]), "+f"(d[3])
        : "r"(a[0]), "r"(a[1]), "r"(a[2]), "r"(a[3]), "r"(b[0]), "r"(b[1]));
}

// C[M,N] = A[M,K] @ B[N,K]^T + bias[N], optional ReLU.
// Both A and B are K-contiguous (row-major [rows, K]) -> row.col MMA.
// Assumes M % BM == 0, N % BN == 0, K % BK == 0 (true for all shapes here).
template <bool RELU>
__global__ void __launch_bounds__(256, 2) gemm_bias_tf32(
    const float* __restrict__ A, const float* __restrict__ Bm,
    const float* __restrict__ bias, float* __restrict__ C,
    int K, int N)
{
    extern __shared__ float sm[];
    float* As = sm;                // [2][BM][BKP]
    float* Bs = sm + 2 * TILE_F;   // [2][BN][BKP]

    const int tid  = threadIdx.x;
    const int lane = tid & 31;
    const int wid  = tid >> 5;
    const int wm   = wid >> 1;     // 0..3 : warp row  (32 M each)
    const int wn   = wid & 1;      // 0..1 : warp col  (64 N each)
    const int g    = lane >> 2;    // 0..7
    const int tg   = lane & 3;     // 0..3

    const int bm = blockIdx.y * BM;
    const int bn = blockIdx.x * BN;

    float acc[2][8][4];
#pragma unroll
    for (int i = 0; i < 2; i++)
#pragma unroll
        for (int j = 0; j < 8; j++)
#pragma unroll
            for (int c = 0; c < 4; c++) acc[i][j][c] = 0.f;

    const int KT = K / BK;

    const uint32_t sA0 = (uint32_t)__cvta_generic_to_shared(As);
    const uint32_t sB0 = (uint32_t)__cvta_generic_to_shared(Bs);

    auto load_tile = [&](int kt, int stage) {
        const float* Ag = A  + (size_t)bm * K + (size_t)kt * BK;
        const float* Bg = Bm + (size_t)bn * K + (size_t)kt * BK;
        const uint32_t sA = sA0 + (uint32_t)stage * TILE_F * 4;
        const uint32_t sB = sB0 + (uint32_t)stage * TILE_F * 4;
#pragma unroll
        for (int t = 0; t < 4; t++) {
            int chunk = tid + t * 256;      // 1024 16B-chunks per tile
            int row = chunk >> 3;           // BK/4 = 8 chunks per row
            int c4  = chunk & 7;
            cp_async16(sA + (uint32_t)(row * BKP + c4 * 4) * 4, Ag + (size_t)row * K + c4 * 4);
            cp_async16(sB + (uint32_t)(row * BKP + c4 * 4) * 4, Bg + (size_t)row * K + c4 * 4);
        }
        cp_commit();
    };

    load_tile(0, 0);

    for (int kt = 0; kt < KT; kt++) {
        const int stage = kt & 1;
        if (kt + 1 < KT) {
            load_tile(kt + 1, stage ^ 1);
            cp_wait<1>();
        } else {
            cp_wait<0>();
        }
        __syncthreads();

        const float* Asb = As + stage * TILE_F;
        const float* Bsb = Bs + stage * TILE_F;

#pragma unroll
        for (int ks = 0; ks < BK / 8; ks++) {
            const int k0 = ks * 8;
            uint32_t af[2][4], bf[8][2];
#pragma unroll
            for (int i = 0; i < 2; i++) {
                const int r = wm * 32 + i * 16 + g;
                af[i][0] = f2tf32(Asb[(r    ) * BKP + k0 + tg    ]);
                af[i][1] = f2tf32(Asb[(r + 8) * BKP + k0 + tg    ]);
                af[i][2] = f2tf32(Asb[(r    ) * BKP + k0 + tg + 4]);
                af[i][3] = f2tf32(Asb[(r + 8) * BKP + k0 + tg + 4]);
            }
#pragma unroll
            for (int j = 0; j < 8; j++) {
                const int c = wn * 64 + j * 8 + g;
                bf[j][0] = f2tf32(Bsb[c * BKP + k0 + tg    ]);
                bf[j][1] = f2tf32(Bsb[c * BKP + k0 + tg + 4]);
            }
#pragma unroll
            for (int i = 0; i < 2; i++)
#pragma unroll
                for (int j = 0; j < 8; j++)
                    mma_tf32(acc[i][j], af[i], bf[j]);
        }
        __syncthreads();
    }

    // Epilogue: +bias, optional ReLU, float2 stores.
#pragma unroll
    for (int i = 0; i < 2; i++) {
        const int r0 = bm + wm * 32 + i * 16 + g;
#pragma unroll
        for (int j = 0; j < 8; j++) {
            const int c = bn + wn * 64 + j * 8 + tg * 2;
            const float bv0 = bias[c];
            const float bv1 = bias[c + 1];
            float v0 = acc[i][j][0] + bv0;
            float v1 = acc[i][j][1] + bv1;
            float v2 = acc[i][j][2] + bv0;
            float v3 = acc[i][j][3] + bv1;
            if (RELU) {
                v0 = fmaxf(v0, 0.f); v1 = fmaxf(v1, 0.f);
                v2 = fmaxf(v2, 0.f); v3 = fmaxf(v3, 0.f);
            }
            *(float2*)(C + (size_t)r0 * N + c)       = make_float2(v0, v1);
            *(float2*)(C + (size_t)(r0 + 8) * N + c) = make_float2(v2, v3);
        }
    }
}

extern "C" void kernel_launch(void* const* d_in, const int* in_sizes, int n_in,
                              void* d_out, int out_size) {
    (void)in_sizes; (void)n_in; (void)out_size;
    const float* x  = (const float*)d_in[0];  // [4,4096,1024] -> [16384,1024]
    const float* W1 = (const float*)d_in[1];  // [4096,1024]
    const float* b1 = (const float*)d_in[2];  // [4096]
    const float* W2 = (const float*)d_in[3];  // [1024,4096]
    const float* b2 = (const float*)d_in[4];  // [1024]
    float* out = (float*)d_out;               // [16384,1024]

    float* inter = nullptr;
    cudaGetSymbolAddress((void**)&inter, g_inter);

    cudaFuncSetAttribute(gemm_bias_tf32<true>,
                         cudaFuncAttributeMaxDynamicSharedMemorySize, SMEM_BYTES);
    cudaFuncSetAttribute(gemm_bias_tf32<false>,
                         cudaFuncAttributeMaxDynamicSharedMemorySize, SMEM_BYTES);

    // GEMM1: inter = ReLU(X @ W1^T + b1)   [16384, 4096], K=1024
    gemm_bias_tf32<true><<<dim3(ITR / BN, MTOT / BM), 256, SMEM_BYTES>>>(
        x, W1, b1, inter, HID, ITR);

    // GEMM2: out = inter @ W2^T + b2       [16384, 1024], K=4096
    gemm_bias_tf32<false><<<dim3(HID / BN, MTOT / BM), 256, SMEM_BYTES>>>(
        inter, W2, b2, out, ITR, HID);
}

// round 3
// speedup vs baseline: 1.0014x; 1.0014x over previous
#include <cuda_runtime.h>
#include <cstdint>

#define HID  1024
#define ITR  4096
#define MTOT 16384

// Intermediate activation buffer (ReLU(X@W1^T + b1)), 16384 x 4096 fp32 = 256 MiB.
__device__ float g_inter[(size_t)MTOT * (size_t)ITR];

#define BM 128
#define BN 128
#define BK 32
#define BKP 36                       // +4 pad: conflict-free fragment LDS
#define TILE_F (BM * BKP)            // floats per (stage, operand) tile
#define SMEM_FLOATS (4 * TILE_F)     // 2 stages x (A + B)
#define SMEM_BYTES (SMEM_FLOATS * 4) // 73728 B

__device__ __forceinline__ void cp_async16(uint32_t saddr, const void* gptr) {
    asm volatile("cp.async.cg.shared.global [%0], [%1], 16;\n" :: "r"(saddr), "l"(gptr));
}
__device__ __forceinline__ void cp_commit() {
    asm volatile("cp.async.commit_group;\n");
}
template <int N>
__device__ __forceinline__ void cp_wait() {
    asm volatile("cp.async.wait_group %0;\n" :: "n"(N));
}

// tf32 round-to-nearest via integer half-ulp bump: HW mma.tf32 ignores the low
// 13 mantissa bits, so bits+0x1000 == cvt.rna.tf32 (up to tie direction) at
// 1 ALU cycle instead of a ~20-cycle converter op on the fma pipe.
__device__ __forceinline__ uint32_t f2tf32(float f) {
    return __float_as_uint(f) + 0x1000u;
}

__device__ __forceinline__ void mma_tf32(float* d, const uint32_t* a, const uint32_t* b) {
    asm volatile(
        "mma.sync.aligned.m16n8k8.row.col.f32.tf32.tf32.f32 "
        "{%0,%1,%2,%3}, {%4,%5,%6,%7}, {%8,%9}, {%0,%1,%2,%3};\n"
        : "+f"(d[0]), "+f"(d[1]), "+f"(d[2]), "+f"(d[3])
        : "r"(a[0]), "r"(a[1]), "r"(a[2]), "r"(a[3]), "r"(b[0]), "r"(b[1]));
}

// C[M,N] = A[M,K] @ B[N,K]^T + bias[N], optional ReLU.
// Both A and B are K-contiguous (row-major [rows, K]) -> row.col MMA.
template <bool RELU>
__global__ void __launch_bounds__(256, 2) gemm_bias_tf32(
    const float* __restrict__ A, const float* __restrict__ Bm,
    const float* __restrict__ bias, float* __restrict__ C,
    int K, int N)
{
    extern __shared__ float sm[];
    float* As = sm;                // [2][BM][BKP]
    float* Bs = sm + 2 * TILE_F;   // [2][BN][BKP]

    const int tid  = threadIdx.x;
    const int lane = tid & 31;
    const int wid  = tid >> 5;
    const int wm   = wid >> 1;     // 0..3 : warp row  (32 M each)
    const int wn   = wid & 1;      // 0..1 : warp col  (64 N each)
    const int g    = lane >> 2;    // 0..7
    const int tg   = lane & 3;     // 0..3

    const int bm = blockIdx.y * BM;
    const int bn = blockIdx.x * BN;

    float acc[2][8][4];
#pragma unroll
    for (int i = 0; i < 2; i++)
#pragma unroll
        for (int j = 0; j < 8; j++)
#pragma unroll
            for (int c = 0; c < 4; c++) acc[i][j][c] = 0.f;

    const int KT = K / BK;

    const uint32_t sA0 = (uint32_t)__cvta_generic_to_shared(As);
    const uint32_t sB0 = (uint32_t)__cvta_generic_to_shared(Bs);

    auto load_tile = [&](int kt, int stage) {
        const float* Ag = A  + (size_t)bm * K + (size_t)kt * BK;
        const float* Bg = Bm + (size_t)bn * K + (size_t)kt * BK;
        const uint32_t sA = sA0 + (uint32_t)stage * TILE_F * 4;
        const uint32_t sB = sB0 + (uint32_t)stage * TILE_F * 4;
#pragma unroll
        for (int t = 0; t < 4; t++) {
            int chunk = tid + t * 256;      // 1024 16B-chunks per tile
            int row = chunk >> 3;           // BK/4 = 8 chunks per row
            int c4  = chunk & 7;
            cp_async16(sA + (uint32_t)(row * BKP + c4 * 4) * 4, Ag + (size_t)row * K + c4 * 4);
            cp_async16(sB + (uint32_t)(row * BKP + c4 * 4) * 4, Bg + (size_t)row * K + c4 * 4);
        }
        cp_commit();
    };

    load_tile(0, 0);

    for (int kt = 0; kt < KT; kt++) {
        const int stage = kt & 1;
        if (kt + 1 < KT) {
            load_tile(kt + 1, stage ^ 1);
            cp_wait<1>();
        } else {
            cp_wait<0>();
        }
        __syncthreads();

        const float* Asb = As + stage * TILE_F;
        const float* Bsb = Bs + stage * TILE_F;

#pragma unroll
        for (int ks = 0; ks < BK / 8; ks++) {
            const int k0 = ks * 8;
            uint32_t af[2][4], bf[8][2];
#pragma unroll
            for (int i = 0; i < 2; i++) {
                const int r = wm * 32 + i * 16 + g;
                af[i][0] = f2tf32(Asb[(r    ) * BKP + k0 + tg    ]);
                af[i][1] = f2tf32(Asb[(r + 8) * BKP + k0 + tg    ]);
                af[i][2] = f2tf32(Asb[(r    ) * BKP + k0 + tg + 4]);
                af[i][3] = f2tf32(Asb[(r + 8) * BKP + k0 + tg + 4]);
            }
#pragma unroll
            for (int j = 0; j < 8; j++) {
                const int c = wn * 64 + j * 8 + g;
                bf[j][0] = f2tf32(Bsb[c * BKP + k0 + tg    ]);
                bf[j][1] = f2tf32(Bsb[c * BKP + k0 + tg + 4]);
            }
#pragma unroll
            for (int i = 0; i < 2; i++)
#pragma unroll
                for (int j = 0; j < 8; j++)
                    mma_tf32(acc[i][j], af[i], bf[j]);
        }
        __syncthreads();
    }

    // Epilogue: +bias, optional ReLU, float2 stores.
#pragma unroll
    for (int i = 0; i < 2; i++) {
        const int r0 = bm + wm * 32 + i * 16 + g;
#pragma unroll
        for (int j = 0; j < 8; j++) {
            const int c = bn + wn * 64 + j * 8 + tg * 2;
            const float bv0 = bias[c];
            const float bv1 = bias[c + 1];
            float v0 = acc[i][j][0] + bv0;
            float v1 = acc[i][j][1] + bv1;
            float v2 = acc[i][j][2] + bv0;
            float v3 = acc[i][j][3] + bv1;
            if (RELU) {
                v0 = fmaxf(v0, 0.f); v1 = fmaxf(v1, 0.f);
                v2 = fmaxf(v2, 0.f); v3 = fmaxf(v3, 0.f);
            }
            *(float2*)(C + (size_t)r0 * N + c)       = make_float2(v0, v1);
            *(float2*)(C + (size_t)(r0 + 8) * N + c) = make_float2(v2, v3);
        }
    }
}

extern "C" void kernel_launch(void* const* d_in, const int* in_sizes, int n_in,
                              void* d_out, int out_size) {
    (void)in_sizes; (void)n_in; (void)out_size;
    const float* x  = (const float*)d_in[0];  // [4,4096,1024] -> [16384,1024]
    const float* W1 = (const float*)d_in[1];  // [4096,1024]
    const float* b1 = (const float*)d_in[2];  // [4096]
    const float* W2 = (const float*)d_in[3];  // [1024,4096]
    const float* b2 = (const float*)d_in[4];  // [1024]
    float* out = (float*)d_out;               // [16384,1024]

    float* inter = nullptr;
    cudaGetSymbolAddress((void**)&inter, g_inter);

    cudaFuncSetAttribute(gemm_bias_tf32<true>,
                         cudaFuncAttributeMaxDynamicSharedMemorySize, SMEM_BYTES);
    cudaFuncSetAttribute(gemm_bias_tf32<false>,
                         cudaFuncAttributeMaxDynamicSharedMemorySize, SMEM_BYTES);

    // GEMM1: inter = ReLU(X @ W1^T + b1)   [16384, 4096], K=1024
    gemm_bias_tf32<true><<<dim3(ITR / BN, MTOT / BM), 256, SMEM_BYTES>>>(
        x, W1, b1, inter, HID, ITR);

    // GEMM2: out = inter @ W2^T + b2       [16384, 1024], K=4096
    gemm_bias_tf32<false><<<dim3(HID / BN, MTOT / BM), 256, SMEM_BYTES>>>(
        inter, W2, b2, out, ITR, HID);
}

// round 4
// speedup vs baseline: 1.0429x; 1.0414x over previous
#include <cuda_runtime.h>
#include <cstdint>

#define HID  1024
#define ITR  4096
#define MTOT 16384

// Intermediate activation buffer (ReLU(X@W1^T + b1)), 16384 x 4096 fp32 = 256 MiB.
__device__ float g_inter[(size_t)MTOT * (size_t)ITR];

#define BM 128
#define BN 128
#define BK 32
#define BKP 36                        // +4 pad: conflict-free fragment LDS
#define STAGES 3
#define TILE_F (BM * BKP)             // floats per (stage, operand) tile
#define SMEM_BYTES (STAGES * 2 * TILE_F * 4)   // 110592 B -> 2 CTAs/SM

__device__ __forceinline__ void cp_async16(uint32_t saddr, const void* gptr) {
    asm volatile("cp.async.cg.shared.global [%0], [%1], 16;\n" :: "r"(saddr), "l"(gptr));
}
__device__ __forceinline__ void cp_commit() {
    asm volatile("cp.async.commit_group;\n");
}
template <int N>
__device__ __forceinline__ void cp_wait() {
    asm volatile("cp.async.wait_group %0;\n" :: "n"(N));
}

// tf32 round-to-nearest via integer half-ulp bump (HW ignores low 13 mantissa bits).
__device__ __forceinline__ uint32_t f2tf32(float f) {
    return __float_as_uint(f) + 0x1000u;
}

__device__ __forceinline__ void mma_tf32(float* d, const uint32_t* a, const uint32_t* b) {
    asm volatile(
        "mma.sync.aligned.m16n8k8.row.col.f32.tf32.tf32.f32 "
        "{%0,%1,%2,%3}, {%4,%5,%6,%7}, {%8,%9}, {%0,%1,%2,%3};\n"
        : "+f"(d[0]), "+f"(d[1]), "+f"(d[2]), "+f"(d[3])
        : "r"(a[0]), "r"(a[1]), "r"(a[2]), "r"(a[3]), "r"(b[0]), "r"(b[1]));
}

// C[M,N] = A[M,K] @ B[N,K]^T + bias[N], optional ReLU.
// 128 threads / CTA, warp grid 2x2, warp tile 64x64 (i=0..3 m16 tiles, j=0..7 n8 tiles).
template <bool RELU>
__global__ void __launch_bounds__(128, 2) gemm_bias_tf32(
    const float* __restrict__ A, const float* __restrict__ Bm,
    const float* __restrict__ bias, float* __restrict__ C,
    int K, int N)
{
    extern __shared__ float sm[];
    // layout: stage s: A at sm + s*2*TILE_F, B at sm + s*2*TILE_F + TILE_F
    const int tid  = threadIdx.x;
    const int lane = tid & 31;
    const int wid  = tid >> 5;
    const int wm   = wid >> 1;     // 0..1 : warp row (64 M each)
    const int wn   = wid & 1;      // 0..1 : warp col (64 N each)
    const int g    = lane >> 2;    // 0..7
    const int tg   = lane & 3;     // 0..3

    const int bm = blockIdx.y * BM;
    const int bn = blockIdx.x * BN;

    float acc[4][8][4];
#pragma unroll
    for (int i = 0; i < 4; i++)
#pragma unroll
        for (int j = 0; j < 8; j++)
#pragma unroll
            for (int c = 0; c < 4; c++) acc[i][j][c] = 0.f;

    const int KT = K / BK;
    const uint32_t s0 = (uint32_t)__cvta_generic_to_shared(sm);

    // 2048 16B-chunks per k-tile (A + B), 16 per thread.
    auto load_tile = [&](int kt, int stage) {
        const float* Ag = A  + (size_t)bm * K + (size_t)kt * BK;
        const float* Bg = Bm + (size_t)bn * K + (size_t)kt * BK;
        const uint32_t sA = s0 + (uint32_t)(stage * 2 * TILE_F) * 4;
        const uint32_t sB = sA + (uint32_t)TILE_F * 4;
#pragma unroll
        for (int t = 0; t < 8; t++) {
            int chunk = tid + t * 128;      // 0..1023
            int row = chunk >> 3;           // BK/4 = 8 chunks per row
            int c4  = chunk & 7;
            cp_async16(sA + (uint32_t)(row * BKP + c4 * 4) * 4, Ag + (size_t)row * K + c4 * 4);
            cp_async16(sB + (uint32_t)(row * BKP + c4 * 4) * 4, Bg + (size_t)row * K + c4 * 4);
        }
        cp_commit();
    };

    load_tile(0, 0);
    load_tile(1, 1);

    uint32_t af[2][4][4], bf[2][8][2];

    for (int kt = 0; kt < KT; kt++) {
        cp_wait<1>();          // stage kt landed (per-thread)
        __syncthreads();       // whole tile landed; stage (kt-1)%3 free to refill

        if (kt + 2 < KT) load_tile(kt + 2, (kt + 2) % STAGES);
        else             cp_commit();   // keep group accounting uniform

        const float* Asb = sm + (kt % STAGES) * 2 * TILE_F;
        const float* Bsb = Asb + TILE_F;

        // fragment prefetch for ks=0
        {
#pragma unroll
            for (int i = 0; i < 4; i++) {
                const int r = wm * 64 + i * 16 + g;
                af[0][i][0] = f2tf32(Asb[(r    ) * BKP + tg    ]);
                af[0][i][1] = f2tf32(Asb[(r + 8) * BKP + tg    ]);
                af[0][i][2] = f2tf32(Asb[(r    ) * BKP + tg + 4]);
                af[0][i][3] = f2tf32(Asb[(r + 8) * BKP + tg + 4]);
            }
#pragma unroll
            for (int j = 0; j < 8; j++) {
                const int c = wn * 64 + j * 8 + g;
                bf[0][j][0] = f2tf32(Bsb[c * BKP + tg    ]);
                bf[0][j][1] = f2tf32(Bsb[c * BKP + tg + 4]);
            }
        }

#pragma unroll
        for (int ks = 0; ks < BK / 8; ks++) {
            const int cur = ks & 1, nxt = cur ^ 1;
            if (ks < BK / 8 - 1) {
                const int k0 = (ks + 1) * 8;
#pragma unroll
                for (int i = 0; i < 4; i++) {
                    const int r = wm * 64 + i * 16 + g;
                    af[nxt][i][0] = f2tf32(Asb[(r    ) * BKP + k0 + tg    ]);
                    af[nxt][i][1] = f2tf32(Asb[(r + 8) * BKP + k0 + tg    ]);
                    af[nxt][i][2] = f2tf32(Asb[(r    ) * BKP + k0 + tg + 4]);
                    af[nxt][i][3] = f2tf32(Asb[(r + 8) * BKP + k0 + tg + 4]);
                }
#pragma unroll
                for (int j = 0; j < 8; j++) {
                    const int c = wn * 64 + j * 8 + g;
                    bf[nxt][j][0] = f2tf32(Bsb[c * BKP + k0 + tg    ]);
                    bf[nxt][j][1] = f2tf32(Bsb[c * BKP + k0 + tg + 4]);
                }
            }
#pragma unroll
            for (int i = 0; i < 4; i++)
#pragma unroll
                for (int j = 0; j < 8; j++)
                    mma_tf32(acc[i][j], af[cur][i], bf[cur][j]);
        }
    }

    // Epilogue: +bias, optional ReLU, float2 stores.
#pragma unroll
    for (int i = 0; i < 4; i++) {
        const int r0 = bm + wm * 64 + i * 16 + g;
#pragma unroll
        for (int j = 0; j < 8; j++) {
            const int c = bn + wn * 64 + j * 8 + tg * 2;
            const float bv0 = bias[c];
            const float bv1 = bias[c + 1];
            float v0 = acc[i][j][0] + bv0;
            float v1 = acc[i][j][1] + bv1;
            float v2 = acc[i][j][2] + bv0;
            float v3 = acc[i][j][3] + bv1;
            if (RELU) {
                v0 = fmaxf(v0, 0.f); v1 = fmaxf(v1, 0.f);
                v2 = fmaxf(v2, 0.f); v3 = fmaxf(v3, 0.f);
            }
            *(float2*)(C + (size_t)r0 * N + c)       = make_float2(v0, v1);
            *(float2*)(C + (size_t)(r0 + 8) * N + c) = make_float2(v2, v3);
        }
    }
}

extern "C" void kernel_launch(void* const* d_in, const int* in_sizes, int n_in,
                              void* d_out, int out_size) {
    (void)in_sizes; (void)n_in; (void)out_size;
    const float* x  = (const float*)d_in[0];  // [4,4096,1024] -> [16384,1024]
    const float* W1 = (const float*)d_in[1];  // [4096,1024]
    const float* b1 = (const float*)d_in[2];  // [4096]
    const float* W2 = (const float*)d_in[3];  // [1024,4096]
    const float* b2 = (const float*)d_in[4];  // [1024]
    float* out = (float*)d_out;               // [16384,1024]

    float* inter = nullptr;
    cudaGetSymbolAddress((void**)&inter, g_inter);

    cudaFuncSetAttribute(gemm_bias_tf32<true>,
                         cudaFuncAttributeMaxDynamicSharedMemorySize, SMEM_BYTES);
    cudaFuncSetAttribute(gemm_bias_tf32<false>,
                         cudaFuncAttributeMaxDynamicSharedMemorySize, SMEM_BYTES);

    // GEMM1: inter = ReLU(X @ W1^T + b1)   [16384, 4096], K=1024
    gemm_bias_tf32<true><<<dim3(ITR / BN, MTOT / BM), 128, SMEM_BYTES>>>(
        x, W1, b1, inter, HID, ITR);

    // GEMM2: out = inter @ W2^T + b2       [16384, 1024], K=4096
    gemm_bias_tf32<false><<<dim3(HID / BN, MTOT / BM), 128, SMEM_BYTES>>>(
        inter, W2, b2, out, ITR, HID);
}